// round 1
// baseline (speedup 1.0000x reference)
#include <cuda_runtime.h>

#define NPTS 8192
#define CH   256
#define KNB  16
#define ASTRIDE 68

// scratch (device globals: no allocation allowed)
__device__ int   g_idx[NPTS * KNB];
__device__ float g_theta[NPTS * CH];
__device__ float g_phi[NPTS * CH];
__device__ float g_gf[NPTS * CH];
__device__ float g_y[NPTS * CH];

__device__ __forceinline__ bool pair_less(float d1, int i1, float d2, int i2) {
    return d1 < d2 || (d1 == d2 && i1 < i2);
}

// ---------------------------------------------------------------------------
// KNN: one warp per query, coords staged in smem as float4(x,y,z,|c|^2).
// d2 = sq_q + sq_j - 2*dot matches the reference formula; (d2, idx)
// lexicographic order matches jax.lax.top_k tie-breaking.
// ---------------------------------------------------------------------------
__global__ __launch_bounds__(512) void knn_kernel(const float* __restrict__ coords) {
    extern __shared__ float4 pts[];
    int tid = threadIdx.x;
    for (int i = tid; i < NPTS; i += 512) {
        float x = coords[3*i+0], y = coords[3*i+1], z = coords[3*i+2];
        pts[i] = make_float4(x, y, z, x*x + y*y + z*z);
    }
    __syncthreads();

    int lane = tid & 31;
    int q = blockIdx.x * 16 + (tid >> 5);
    float4 qp = pts[q];

    float bd[KNB]; int bi[KNB];
#pragma unroll
    for (int t = 0; t < KNB; ++t) { bd[t] = 3.4e38f; bi[t] = 0x7fffffff; }

#pragma unroll 4
    for (int j = lane; j < NPTS; j += 32) {
        float4 p = pts[j];
        float d = qp.w + p.w - 2.0f * (qp.x*p.x + qp.y*p.y + qp.z*p.z);
        if (pair_less(d, j, bd[KNB-1], bi[KNB-1])) {
            float cd = d; int ci = j;
#pragma unroll
            for (int t = 0; t < KNB; ++t) {
                bool sw = pair_less(cd, ci, bd[t], bi[t]);
                float td = sw ? bd[t] : cd; int ti = sw ? bi[t] : ci;
                bd[t] = sw ? cd : bd[t];   bi[t] = sw ? ci : bi[t];
                cd = td; ci = ti;
            }
        }
    }

    // warp merge: 16 rounds of min-reduce over per-lane sorted heads
    float hd = bd[0]; int hi = bi[0];
    for (int k = 0; k < KNB; ++k) {
        float md = hd; int mi = hi;
#pragma unroll
        for (int off = 16; off; off >>= 1) {
            float od = __shfl_xor_sync(0xffffffffu, md, off);
            int   oi = __shfl_xor_sync(0xffffffffu, mi, off);
            if (pair_less(od, oi, md, mi)) { md = od; mi = oi; }
        }
        if (lane == 0) g_idx[q * KNB + k] = mi;
        if (hd == md && hi == mi) {   // unique winner (indices disjoint per lane)
#pragma unroll
            for (int t = 0; t < KNB-1; ++t) { bd[t] = bd[t+1]; bi[t] = bi[t+1]; }
            bd[KNB-1] = 3.4e38f; bi[KNB-1] = 0x7fffffff;
            hd = bd[0]; hi = bi[0];
        }
    }
}

// ---------------------------------------------------------------------------
// fp32 tiled GEMM: out[M,N] = A[M,K] @ B[K,N] + bias[N] (+ resid[M,N]).
// Block tile 64x64, thread tile 4x4, K-tile 16. M=8192, K=N=256 here.
// ---------------------------------------------------------------------------
__global__ __launch_bounds__(256) void gemm_kernel(
    const float* __restrict__ A, const float* __restrict__ B,
    const float* __restrict__ bias, const float* __restrict__ resid,
    float* __restrict__ outp, int Kd, int Nn)
{
    __shared__ __align__(16) float As[16][ASTRIDE];
    __shared__ __align__(16) float Bs[16][64];
    int tid = threadIdx.x;
    int tx = tid & 15, ty = tid >> 4;
    int m0 = blockIdx.y * 64, n0 = blockIdx.x * 64;

    float acc[4][4] = {};
    int arow = tid >> 2, akq = (tid & 3) * 4;
    int brow = tid >> 4, bc  = (tid & 15) * 4;

    for (int k0 = 0; k0 < Kd; k0 += 16) {
        float4 areg = *(const float4*)&A[(m0 + arow) * Kd + k0 + akq];
        float4 breg = *(const float4*)&B[(k0 + brow) * Nn + n0 + bc];
        __syncthreads();   // previous tile fully consumed
        As[akq+0][arow] = areg.x; As[akq+1][arow] = areg.y;
        As[akq+2][arow] = areg.z; As[akq+3][arow] = areg.w;
        *(float4*)&Bs[brow][bc] = breg;
        __syncthreads();
#pragma unroll
        for (int kk = 0; kk < 16; ++kk) {
            float4 av = *(const float4*)&As[kk][ty * 4];
            float4 bv = *(const float4*)&Bs[kk][tx * 4];
            float aa[4] = {av.x, av.y, av.z, av.w};
            float bb[4] = {bv.x, bv.y, bv.z, bv.w};
#pragma unroll
            for (int i = 0; i < 4; ++i)
#pragma unroll
                for (int j = 0; j < 4; ++j)
                    acc[i][j] = fmaf(aa[i], bb[j], acc[i][j]);
        }
    }

    float4 bi4 = *(const float4*)&bias[n0 + tx * 4];
    float bb[4] = {bi4.x, bi4.y, bi4.z, bi4.w};
#pragma unroll
    for (int i = 0; i < 4; ++i) {
        int m = m0 + ty * 4 + i;
        float4 o;
        o.x = acc[i][0] + bb[0]; o.y = acc[i][1] + bb[1];
        o.z = acc[i][2] + bb[2]; o.w = acc[i][3] + bb[3];
        if (resid) {
            float4 r = *(const float4*)&resid[m * Nn + n0 + tx * 4];
            o.x += r.x; o.y += r.y; o.z += r.z; o.w += r.w;
        }
        *(float4*)&outp[m * Nn + n0 + tx * 4] = o;
    }
}

// ---------------------------------------------------------------------------
// Fused attention: block = 4 points (64 (n,k) rows).
// Phase 1: pe = relu(dc@W1+b1)@W2 + b2 via register-tiled GEMM (H built on
//          the fly in smem: only 3 FMA + relu per element).
// Phase 2: logits, softmax over K, y = sum(sim * g_gather).
// ---------------------------------------------------------------------------
__global__ __launch_bounds__(256, 2) void attn_kernel(
    const float* __restrict__ coords,
    const float* __restrict__ pw1, const float* __restrict__ pb1,
    const float* __restrict__ pw2, const float* __restrict__ pb2)
{
    extern __shared__ __align__(16) float sm[];
    float* pe_s = sm;                       // 64*256
    float* Bs   = sm + 64 * CH;             // 16*256
    float* Hs   = Bs + 16 * CH;             // 16*ASTRIDE
    float* dc_s = Hs + 16 * ASTRIDE;        // 64*4
    int*   js   = (int*)(dc_s + 64 * 4);    // 64

    int tid = threadIdx.x;
    int n0 = blockIdx.x * 4;

    if (tid < 64) {
        int p = tid >> 4, k = tid & 15;
        int n = n0 + p;
        int j = g_idx[n * KNB + k];
        js[tid] = j;
        dc_s[tid*4+0] = coords[3*j+0] - coords[3*n+0];
        dc_s[tid*4+1] = coords[3*j+1] - coords[3*n+1];
        dc_s[tid*4+2] = coords[3*j+2] - coords[3*n+2];
    }
    __syncthreads();

    int rg = tid >> 5, cg = tid & 31;        // 8 row-groups x 32 col-groups
    int hh = tid >> 4, r0 = (tid & 15) * 4;  // H producer mapping

    float acc[8][8];
#pragma unroll
    for (int i = 0; i < 8; ++i)
#pragma unroll
        for (int j = 0; j < 8; ++j) acc[i][j] = 0.f;

    for (int k0 = 0; k0 < CH; k0 += 16) {
        float4 wreg[4];
#pragma unroll
        for (int u = 0; u < 4; ++u) {
            int l = tid + 256 * u;
            int r = l >> 6, c4 = l & 63;
            wreg[u] = *(const float4*)&pw2[(k0 + r) * CH + c4 * 4];
        }
        float w0 = pw1[k0 + hh], w1 = pw1[CH + k0 + hh], w2 = pw1[2*CH + k0 + hh];
        float b1v = pb1[k0 + hh];
        __syncthreads();   // previous tile consumed
#pragma unroll
        for (int u = 0; u < 4; ++u) {
            int l = tid + 256 * u;
            int r = l >> 6, c4 = l & 63;
            *(float4*)&Bs[r * CH + c4 * 4] = wreg[u];
        }
#pragma unroll
        for (int u = 0; u < 4; ++u) {
            int r = r0 + u;
            float h = fmaf(dc_s[r*4+0], w0,
                      fmaf(dc_s[r*4+1], w1,
                      fmaf(dc_s[r*4+2], w2, b1v)));
            Hs[hh * ASTRIDE + r] = fmaxf(h, 0.f);
        }
        __syncthreads();
#pragma unroll
        for (int kk = 0; kk < 16; ++kk) {
            float av[8], bv[8];
            *(float4*)&av[0] = *(const float4*)&Hs[kk * ASTRIDE + rg * 8];
            *(float4*)&av[4] = *(const float4*)&Hs[kk * ASTRIDE + rg * 8 + 4];
            *(float4*)&bv[0] = *(const float4*)&Bs[kk * CH + cg * 8];
            *(float4*)&bv[4] = *(const float4*)&Bs[kk * CH + cg * 8 + 4];
#pragma unroll
            for (int i = 0; i < 8; ++i)
#pragma unroll
                for (int j = 0; j < 8; ++j)
                    acc[i][j] = fmaf(av[i], bv[j], acc[i][j]);
        }
    }

    // pe -> smem (+ b2)
    float4 p20 = *(const float4*)&pb2[cg * 8];
    float4 p21 = *(const float4*)&pb2[cg * 8 + 4];
    float b2v[8] = {p20.x, p20.y, p20.z, p20.w, p21.x, p21.y, p21.z, p21.w};
#pragma unroll
    for (int i = 0; i < 8; ++i) {
        int row = rg * 8 + i;
        float4 o0, o1;
        o0.x = acc[i][0] + b2v[0]; o0.y = acc[i][1] + b2v[1];
        o0.z = acc[i][2] + b2v[2]; o0.w = acc[i][3] + b2v[3];
        o1.x = acc[i][4] + b2v[4]; o1.y = acc[i][5] + b2v[5];
        o1.z = acc[i][6] + b2v[6]; o1.w = acc[i][7] + b2v[7];
        *(float4*)&pe_s[row * CH + cg * 8]     = o0;
        *(float4*)&pe_s[row * CH + cg * 8 + 4] = o1;
    }
    __syncthreads();

    // Phase 2: softmax over K + weighted g sum; thread = channel
    const float inv = 0.0625f;  // 1/sqrt(256)
    int c = tid;
#pragma unroll 1
    for (int p = 0; p < 4; ++p) {
        int n = n0 + p;
        float th = g_theta[n * CH + c];
        float lv[KNB];
        float mx = -3.4e38f;
#pragma unroll
        for (int k = 0; k < KNB; ++k) {
            int j = js[p * KNB + k];
            float pe = pe_s[(p * KNB + k) * CH + c];
            float ph = g_phi[j * CH + c];
            float v = fmaf(pe, th - ph, pe) * inv;
            lv[k] = v;
            mx = fmaxf(mx, v);
        }
        float s = 0.f, ya = 0.f;
#pragma unroll
        for (int k = 0; k < KNB; ++k) {
            int j = js[p * KNB + k];
            float e = __expf(lv[k] - mx);
            s += e;
            ya = fmaf(e, g_gf[j * CH + c], ya);
        }
        g_y[n * CH + c] = ya / s;
    }
}

// ---------------------------------------------------------------------------
extern "C" void kernel_launch(void* const* d_in, const int* in_sizes, int n_in,
                              void* d_out, int out_size)
{
    const float* coords  = (const float*)d_in[0];
    const float* feats   = (const float*)d_in[1];
    const float* theta_w = (const float*)d_in[2];
    const float* theta_b = (const float*)d_in[3];
    const float* phi_w   = (const float*)d_in[4];
    const float* phi_b   = (const float*)d_in[5];
    const float* g_w     = (const float*)d_in[6];
    const float* g_b     = (const float*)d_in[7];
    const float* pe1_w1  = (const float*)d_in[8];
    const float* pe1_b1  = (const float*)d_in[9];
    const float* pe1_w2  = (const float*)d_in[10];
    const float* pe1_b2  = (const float*)d_in[11];
    const float* W_w     = (const float*)d_in[12];
    const float* W_b     = (const float*)d_in[13];
    float* out = (float*)d_out;

    float *p_theta, *p_phi, *p_g, *p_y;
    cudaGetSymbolAddress((void**)&p_theta, g_theta);
    cudaGetSymbolAddress((void**)&p_phi,   g_phi);
    cudaGetSymbolAddress((void**)&p_g,     g_gf);
    cudaGetSymbolAddress((void**)&p_y,     g_y);

    const int knn_smem  = NPTS * 16;                           // 128 KB
    const int attn_smem = (64*CH + 16*CH + 16*ASTRIDE + 64*4) * 4 + 64 * 4;

    cudaFuncSetAttribute((const void*)knn_kernel,
                         cudaFuncAttributeMaxDynamicSharedMemorySize, knn_smem);
    cudaFuncSetAttribute((const void*)attn_kernel,
                         cudaFuncAttributeMaxDynamicSharedMemorySize, attn_smem);

    knn_kernel<<<NPTS / 16, 512, knn_smem>>>(coords);

    dim3 ggrid(CH / 64, NPTS / 64);
    gemm_kernel<<<ggrid, 256>>>(feats, theta_w, theta_b, nullptr, p_theta, CH, CH);
    gemm_kernel<<<ggrid, 256>>>(feats, phi_w,   phi_b,   nullptr, p_phi,   CH, CH);
    gemm_kernel<<<ggrid, 256>>>(feats, g_w,     g_b,     nullptr, p_g,     CH, CH);

    attn_kernel<<<NPTS / 4, 256, attn_smem>>>(coords, pe1_w1, pe1_b1, pe1_w2, pe1_b2);

    gemm_kernel<<<ggrid, 256>>>(p_y, W_w, W_b, feats, out, CH, CH);
}

// round 3
// speedup vs baseline: 1.2357x; 1.2357x over previous
#include <cuda_runtime.h>
#include <cuda_bf16.h>
#include <cstdint>

#define NPTS 8192
#define CH   256
#define KNB  16
#define ASTRIDE 68

// scratch (device globals: no allocation allowed)
__device__ int   g_idx[NPTS * KNB];
__device__ float g_theta[NPTS * CH];
__device__ float g_phi[NPTS * CH];
__device__ float g_gf[NPTS * CH];
__device__ float g_y[NPTS * CH];

__device__ __forceinline__ bool pair_less(float d1, int i1, float d2, int i2) {
    return d1 < d2 || (d1 == d2 && i1 < i2);
}

__device__ __forceinline__ uint32_t smem_u32(const void* p) {
    uint32_t a;
    asm("{ .reg .u64 t; cvta.to.shared.u64 t, %1; cvt.u32.u64 %0, t; }" : "=r"(a) : "l"(p));
    return a;
}

// ---------------------------------------------------------------------------
// KNN: one warp per query, coords staged in smem as float4(x,y,z,|c|^2).
// ---------------------------------------------------------------------------
__global__ __launch_bounds__(512) void knn_kernel(const float* __restrict__ coords) {
    extern __shared__ float4 pts[];
    int tid = threadIdx.x;
    for (int i = tid; i < NPTS; i += 512) {
        float x = coords[3*i+0], y = coords[3*i+1], z = coords[3*i+2];
        pts[i] = make_float4(x, y, z, x*x + y*y + z*z);
    }
    __syncthreads();

    int lane = tid & 31;
    int q = blockIdx.x * 16 + (tid >> 5);
    float4 qp = pts[q];

    float bd[KNB]; int bi[KNB];
#pragma unroll
    for (int t = 0; t < KNB; ++t) { bd[t] = 3.4e38f; bi[t] = 0x7fffffff; }

#pragma unroll 4
    for (int j = lane; j < NPTS; j += 32) {
        float4 p = pts[j];
        float d = qp.w + p.w - 2.0f * (qp.x*p.x + qp.y*p.y + qp.z*p.z);
        if (pair_less(d, j, bd[KNB-1], bi[KNB-1])) {
            float cd = d; int ci = j;
#pragma unroll
            for (int t = 0; t < KNB; ++t) {
                bool sw = pair_less(cd, ci, bd[t], bi[t]);
                float td = sw ? bd[t] : cd; int ti = sw ? bi[t] : ci;
                bd[t] = sw ? cd : bd[t];   bi[t] = sw ? ci : bi[t];
                cd = td; ci = ti;
            }
        }
    }

    float hd = bd[0]; int hi = bi[0];
    for (int k = 0; k < KNB; ++k) {
        float md = hd; int mi = hi;
#pragma unroll
        for (int off = 16; off; off >>= 1) {
            float od = __shfl_xor_sync(0xffffffffu, md, off);
            int   oi = __shfl_xor_sync(0xffffffffu, mi, off);
            if (pair_less(od, oi, md, mi)) { md = od; mi = oi; }
        }
        if (lane == 0) g_idx[q * KNB + k] = mi;
        if (hd == md && hi == mi) {
#pragma unroll
            for (int t = 0; t < KNB-1; ++t) { bd[t] = bd[t+1]; bi[t] = bi[t+1]; }
            bd[KNB-1] = 3.4e38f; bi[KNB-1] = 0x7fffffff;
            hd = bd[0]; hi = bi[0];
        }
    }
}

// ---------------------------------------------------------------------------
// fp32 tiled GEMM (theta/phi/g and final W+residual)
// ---------------------------------------------------------------------------
__global__ __launch_bounds__(256) void gemm_kernel(
    const float* __restrict__ A, const float* __restrict__ B,
    const float* __restrict__ bias, const float* __restrict__ resid,
    float* __restrict__ outp, int Kd, int Nn)
{
    __shared__ __align__(16) float As[16][ASTRIDE];
    __shared__ __align__(16) float Bs[16][64];
    int tid = threadIdx.x;
    int tx = tid & 15, ty = tid >> 4;
    int m0 = blockIdx.y * 64, n0 = blockIdx.x * 64;

    float acc[4][4] = {};
    int arow = tid >> 2, akq = (tid & 3) * 4;
    int brow = tid >> 4, bc  = (tid & 15) * 4;

    for (int k0 = 0; k0 < Kd; k0 += 16) {
        float4 areg = *(const float4*)&A[(m0 + arow) * Kd + k0 + akq];
        float4 breg = *(const float4*)&B[(k0 + brow) * Nn + n0 + bc];
        __syncthreads();
        As[akq+0][arow] = areg.x; As[akq+1][arow] = areg.y;
        As[akq+2][arow] = areg.z; As[akq+3][arow] = areg.w;
        *(float4*)&Bs[brow][bc] = breg;
        __syncthreads();
#pragma unroll
        for (int kk = 0; kk < 16; ++kk) {
            float4 av = *(const float4*)&As[kk][ty * 4];
            float4 bv = *(const float4*)&Bs[kk][tx * 4];
            float aa[4] = {av.x, av.y, av.z, av.w};
            float bb[4] = {bv.x, bv.y, bv.z, bv.w};
#pragma unroll
            for (int i = 0; i < 4; ++i)
#pragma unroll
                for (int j = 0; j < 4; ++j)
                    acc[i][j] = fmaf(aa[i], bb[j], acc[i][j]);
        }
    }

    float4 bi4 = *(const float4*)&bias[n0 + tx * 4];
    float bb[4] = {bi4.x, bi4.y, bi4.z, bi4.w};
#pragma unroll
    for (int i = 0; i < 4; ++i) {
        int m = m0 + ty * 4 + i;
        float4 o;
        o.x = acc[i][0] + bb[0]; o.y = acc[i][1] + bb[1];
        o.z = acc[i][2] + bb[2]; o.w = acc[i][3] + bb[3];
        if (resid) {
            float4 r = *(const float4*)&resid[m * Nn + n0 + tx * 4];
            o.x += r.x; o.y += r.y; o.z += r.z; o.w += r.w;
        }
        *(float4*)&outp[m * Nn + n0 + tx * 4] = o;
    }
}

// ===========================================================================
// Fused attention via mma.sync bf16 (HMMA).
// Block = 8 points (M=128 rows), 256 threads, warp w owns point w.
// H[128][256] bf16 in smem (stride 264), W2 chunk [256][64] k-major bf16
// (stride 72). A frags: ldmatrix.x4; B frags: ldmatrix.x2.trans.
// Softmax over 16 neighbors lives in C-fragment rows (3 xor-shuffles).
// ===========================================================================
#define OFF_JS   0
#define OFF_DC   512
#define OFF_W1   2048
#define OFF_H    6144
#define HSTR_B   528
#define OFF_W2   73728
#define WSTR_B   144
#define ATTN_SMEM 110592

__global__ __launch_bounds__(256, 2) void attn_kernel(
    const float* __restrict__ coords,
    const float* __restrict__ pw1, const float* __restrict__ pb1,
    const float* __restrict__ pw2, const float* __restrict__ pb2)
{
    extern __shared__ __align__(16) char sm[];
    int*    js  = (int*)(sm + OFF_JS);
    float*  dc0 = (float*)(sm + OFF_DC);
    float*  dc1 = dc0 + 128;
    float*  dc2 = dc0 + 256;
    float4* w1f = (float4*)(sm + OFF_W1);

    const int tid  = threadIdx.x;
    const int lane = tid & 31;
    const int wp   = tid >> 5;          // warp = point
    const int n0   = blockIdx.x * 8;

    // neighbor indices + delta coords (rows m = p*16 + k)
    if (tid < 128) {
        int p = tid >> 4, k = tid & 15;
        int n = n0 + p;
        int j = g_idx[n * KNB + k];
        js[tid] = j;
        dc0[tid] = coords[3*j+0] - coords[3*n+0];
        dc1[tid] = coords[3*j+1] - coords[3*n+1];
        dc2[tid] = coords[3*j+2] - coords[3*n+2];
    }
    w1f[tid] = make_float4(pw1[tid], pw1[CH + tid], pw1[2*CH + tid], pb1[tid]);
    __syncthreads();

    // Build H[m][k] = relu(dc . W1col + b1), bf16 pairs
    for (int it = tid; it < 128 * 128; it += 256) {
        int m = it >> 7, q = it & 127;
        float4 wa = w1f[2*q], wb = w1f[2*q + 1];
        float d0 = dc0[m], d1 = dc1[m], d2 = dc2[m];
        float h0 = fmaxf(fmaf(d0, wa.x, fmaf(d1, wa.y, fmaf(d2, wa.z, wa.w))), 0.f);
        float h1 = fmaxf(fmaf(d0, wb.x, fmaf(d1, wb.y, fmaf(d2, wb.z, wb.w))), 0.f);
        *(__nv_bfloat162*)(sm + OFF_H + m * HSTR_B + q * 4) = __floats2bfloat162_rn(h0, h1);
    }

    const uint32_t sbase = smem_u32(sm);
    const uint32_t aAddrBase = sbase + OFF_H +
        (uint32_t)(wp * 16 + (lane & 15)) * HSTR_B + (uint32_t)(lane >> 4) * 16;
    const uint32_t bAddrBase = sbase + OFF_W2 + (uint32_t)(lane & 15) * WSTR_B;

    const int r1 = lane >> 2;
    const int m1 = wp * 16 + r1, m2 = m1 + 8;
    const float inv = 0.0625f;   // 1/sqrt(256)

    for (int nc = 0; nc < 4; ++nc) {
        const int nbase = nc * 64;
        __syncthreads();   // previous chunk's mma done (and H complete on nc=0)
        // stage W2[k 0..255][n chunk of 64] as k-major bf16, stride 72
        for (int it = tid; it < 8192; it += 256) {
            int q = it & 31, k = it >> 5;
            float2 v = *(const float2*)&pw2[k * CH + nbase + 2 * q];
            *(__nv_bfloat162*)(sm + OFF_W2 + k * WSTR_B + q * 4) =
                __floats2bfloat162_rn(v.x, v.y);
        }
        __syncthreads();

        float acc[8][4];
#pragma unroll
        for (int t = 0; t < 8; ++t)
#pragma unroll
            for (int i = 0; i < 4; ++i) acc[t][i] = 0.f;

#pragma unroll 4
        for (int kt = 0; kt < 16; ++kt) {
            uint32_t a0, a1, a2, a3;
            asm volatile("ldmatrix.sync.aligned.m8n8.x4.shared.b16 {%0,%1,%2,%3}, [%4];"
                         : "=r"(a0), "=r"(a1), "=r"(a2), "=r"(a3)
                         : "r"(aAddrBase + (uint32_t)kt * 32));
#pragma unroll
            for (int t = 0; t < 8; ++t) {
                uint32_t b0, b1;
                asm volatile("ldmatrix.sync.aligned.m8n8.x2.trans.shared.b16 {%0,%1}, [%2];"
                             : "=r"(b0), "=r"(b1)
                             : "r"(bAddrBase + (uint32_t)kt * (16 * WSTR_B) + (uint32_t)t * 16));
                asm volatile("mma.sync.aligned.m16n8k16.row.col.f32.bf16.bf16.f32 "
                             "{%0,%1,%2,%3}, {%4,%5,%6,%7}, {%8,%9}, {%0,%1,%2,%3};"
                             : "+f"(acc[t][0]), "+f"(acc[t][1]), "+f"(acc[t][2]), "+f"(acc[t][3])
                             : "r"(a0), "r"(a1), "r"(a2), "r"(a3), "r"(b0), "r"(b1));
            }
        }

        // Epilogue: logits, softmax over 16 rows, weighted g-sum
        const int j1 = js[m1], j2 = js[m2];
        const float* thp = g_theta + (size_t)(n0 + wp) * CH;
#pragma unroll
        for (int t = 0; t < 8; ++t) {
            int ca = nbase + t * 8 + 2 * (lane & 3);
            float2 th  = *(const float2*)&thp[ca];
            float2 b2  = *(const float2*)&pb2[ca];
            float2 p1  = *(const float2*)&g_phi[(size_t)j1 * CH + ca];
            float2 p2  = *(const float2*)&g_phi[(size_t)j2 * CH + ca];
            float2 gg1 = *(const float2*)&g_gf [(size_t)j1 * CH + ca];
            float2 gg2 = *(const float2*)&g_gf [(size_t)j2 * CH + ca];
            float pe00 = acc[t][0] + b2.x, pe01 = acc[t][1] + b2.y;
            float pe10 = acc[t][2] + b2.x, pe11 = acc[t][3] + b2.y;
            float v00 = fmaf(pe00, th.x - p1.x, pe00) * inv;
            float v01 = fmaf(pe01, th.y - p1.y, pe01) * inv;
            float v10 = fmaf(pe10, th.x - p2.x, pe10) * inv;
            float v11 = fmaf(pe11, th.y - p2.y, pe11) * inv;
            float mx = fmaxf(fmaxf(v00, v01), fmaxf(v10, v11));
#pragma unroll
            for (int off = 4; off <= 16; off <<= 1)
                mx = fmaxf(mx, __shfl_xor_sync(0xffffffffu, mx, off));
            float e00 = __expf(v00 - mx), e01 = __expf(v01 - mx);
            float e10 = __expf(v10 - mx), e11 = __expf(v11 - mx);
            float sa = e00 + e10, sb = e01 + e11;
            float ya = fmaf(e00, gg1.x, e10 * gg2.x);
            float yb = fmaf(e01, gg1.y, e11 * gg2.y);
#pragma unroll
            for (int off = 4; off <= 16; off <<= 1) {
                sa += __shfl_xor_sync(0xffffffffu, sa, off);
                sb += __shfl_xor_sync(0xffffffffu, sb, off);
                ya += __shfl_xor_sync(0xffffffffu, ya, off);
                yb += __shfl_xor_sync(0xffffffffu, yb, off);
            }
            if (lane < 4)
                *(float2*)&g_y[(size_t)(n0 + wp) * CH + ca] = make_float2(ya / sa, yb / sb);
        }
    }
}

// ---------------------------------------------------------------------------
extern "C" void kernel_launch(void* const* d_in, const int* in_sizes, int n_in,
                              void* d_out, int out_size)
{
    const float* coords  = (const float*)d_in[0];
    const float* feats   = (const float*)d_in[1];
    const float* theta_w = (const float*)d_in[2];
    const float* theta_b = (const float*)d_in[3];
    const float* phi_w   = (const float*)d_in[4];
    const float* phi_b   = (const float*)d_in[5];
    const float* g_w     = (const float*)d_in[6];
    const float* g_b     = (const float*)d_in[7];
    const float* pe1_w1  = (const float*)d_in[8];
    const float* pe1_b1  = (const float*)d_in[9];
    const float* pe1_w2  = (const float*)d_in[10];
    const float* pe1_b2  = (const float*)d_in[11];
    const float* W_w     = (const float*)d_in[12];
    const float* W_b     = (const float*)d_in[13];
    float* out = (float*)d_out;

    float *p_theta, *p_phi, *p_g, *p_y;
    cudaGetSymbolAddress((void**)&p_theta, g_theta);
    cudaGetSymbolAddress((void**)&p_phi,   g_phi);
    cudaGetSymbolAddress((void**)&p_g,     g_gf);
    cudaGetSymbolAddress((void**)&p_y,     g_y);

    const int knn_smem = NPTS * 16;   // 128 KB

    cudaFuncSetAttribute((const void*)knn_kernel,
                         cudaFuncAttributeMaxDynamicSharedMemorySize, knn_smem);
    cudaFuncSetAttribute((const void*)attn_kernel,
                         cudaFuncAttributeMaxDynamicSharedMemorySize, ATTN_SMEM);

    knn_kernel<<<NPTS / 16, 512, knn_smem>>>(coords);

    dim3 ggrid(CH / 64, NPTS / 64);
    gemm_kernel<<<ggrid, 256>>>(feats, theta_w, theta_b, nullptr, p_theta, CH, CH);
    gemm_kernel<<<ggrid, 256>>>(feats, phi_w,   phi_b,   nullptr, p_phi,   CH, CH);
    gemm_kernel<<<ggrid, 256>>>(feats, g_w,     g_b,     nullptr, p_g,     CH, CH);

    attn_kernel<<<NPTS / 8, 256, ATTN_SMEM>>>(coords, pe1_w1, pe1_b1, pe1_w2, pe1_b2);

    gemm_kernel<<<ggrid, 256>>>(p_y, W_w, W_b, feats, out, CH, CH);
}

// round 5
// speedup vs baseline: 3.2006x; 2.5900x over previous
#include <cuda_runtime.h>
#include <cuda_bf16.h>
#include <cstdint>

#define NPTS 8192
#define CH   256
#define KNB  16
#define ASTRIDE 68

#define GRID   8
#define NCELLS 512
#define CELLSZ 12.5f
#define INVCELL 0.08f

// scratch (device globals: no allocation allowed)
__device__ int   g_idx[NPTS * KNB];
__device__ float g_theta[NPTS * CH];
__device__ float g_phi[NPTS * CH];
__device__ float g_gf[NPTS * CH];
__device__ float g_y[NPTS * CH];

__device__ int    g_cellCnt[NCELLS];
__device__ int    g_cellStart[NCELLS];
__device__ int    g_cellOffs[NCELLS];
__device__ float4 g_spts[NPTS];
__device__ int    g_sidx[NPTS];
__device__ int    g_pcell[NPTS];

__device__ __forceinline__ bool pair_less(float d1, int i1, float d2, int i2) {
    return d1 < d2 || (d1 == d2 && i1 < i2);
}

__device__ __forceinline__ int cell_of(float x) {
    int c = (int)(x * INVCELL);
    return c < 0 ? 0 : (c > GRID - 1 ? GRID - 1 : c);
}

__device__ __forceinline__ uint32_t smem_u32(const void* p) {
    uint32_t a;
    asm("{ .reg .u64 t; cvta.to.shared.u64 t, %1; cvt.u32.u64 %0, t; }" : "=r"(a) : "l"(p));
    return a;
}

// ---------------------------------------------------------------------------
// Grid build
// ---------------------------------------------------------------------------
__global__ void grid_zero_kernel() {
    g_cellCnt[threadIdx.x] = 0;
}

__global__ void grid_count_kernel(const float* __restrict__ coords) {
    int i = blockIdx.x * 256 + threadIdx.x;
    float x = coords[3*i+0], y = coords[3*i+1], z = coords[3*i+2];
    int c = (cell_of(z) * GRID + cell_of(y)) * GRID + cell_of(x);
    g_pcell[i] = c;
    atomicAdd(&g_cellCnt[c], 1);
}

__global__ void grid_prefix_kernel() {
    __shared__ int tmp[NCELLS];
    int t = threadIdx.x;
    int v = g_cellCnt[t];
    tmp[t] = v;
    __syncthreads();
    for (int off = 1; off < NCELLS; off <<= 1) {
        int a = (t >= off) ? tmp[t - off] : 0;
        __syncthreads();
        tmp[t] += a;
        __syncthreads();
    }
    int excl = tmp[t] - v;
    g_cellStart[t] = excl;
    g_cellOffs[t]  = excl;
}

__global__ void grid_scatter_kernel(const float* __restrict__ coords) {
    int i = blockIdx.x * 256 + threadIdx.x;
    float x = coords[3*i+0], y = coords[3*i+1], z = coords[3*i+2];
    int c = g_pcell[i];
    int pos = atomicAdd(&g_cellOffs[c], 1);
    g_spts[pos] = make_float4(x, y, z, x*x + y*y + z*z);
    g_sidx[pos] = i;
}

// ---------------------------------------------------------------------------
// Grid KNN: one warp per query; scan (2R+1)^3 cell block, exactness check,
// expand R if the 16th distance could reach beyond the scanned block.
// ---------------------------------------------------------------------------
__global__ __launch_bounds__(256) void knn_grid_kernel(const float* __restrict__ coords) {
    int tid  = threadIdx.x;
    int lane = tid & 31;
    int q    = blockIdx.x * 8 + (tid >> 5);

    float qx = coords[3*q+0], qy = coords[3*q+1], qz = coords[3*q+2];
    float qsq = qx*qx + qy*qy + qz*qz;
    int cx = cell_of(qx), cy = cell_of(qy), cz = cell_of(qz);

    for (int R = 1; R <= GRID; ++R) {
        float bd[KNB]; int bi[KNB];
#pragma unroll
        for (int t = 0; t < KNB; ++t) { bd[t] = 3.4e38f; bi[t] = 0x7fffffff; }

        int x0 = max(cx - R, 0), x1 = min(cx + R, GRID - 1);
        int y0 = max(cy - R, 0), y1 = min(cy + R, GRID - 1);
        int z0 = max(cz - R, 0), z1 = min(cz + R, GRID - 1);

        for (int zz = z0; zz <= z1; ++zz)
        for (int yy = y0; yy <= y1; ++yy)
        for (int xx = x0; xx <= x1; ++xx) {
            int cell  = (zz * GRID + yy) * GRID + xx;
            int start = g_cellStart[cell];
            int cnt   = g_cellCnt[cell];
            for (int b = 0; b < cnt; b += 32) {
                int i = b + lane;
                if (i < cnt) {
                    float4 p = g_spts[start + i];
                    int j = g_sidx[start + i];
                    float d = qsq + p.w - 2.0f * (qx*p.x + qy*p.y + qz*p.z);
                    if (pair_less(d, j, bd[KNB-1], bi[KNB-1])) {
                        float cd = d; int ci = j;
#pragma unroll
                        for (int t = 0; t < KNB; ++t) {
                            bool sw = pair_less(cd, ci, bd[t], bi[t]);
                            float td = sw ? bd[t] : cd; int ti = sw ? bi[t] : ci;
                            bd[t] = sw ? cd : bd[t];   bi[t] = sw ? ci : bi[t];
                            cd = td; ci = ti;
                        }
                    }
                }
            }
        }

        // warp merge: 16 rounds of min-reduce over per-lane sorted heads
        float hd = bd[0]; int hi = bi[0];
        float r16 = 3.4e38f;
        for (int k = 0; k < KNB; ++k) {
            float md = hd; int mi = hi;
#pragma unroll
            for (int off = 16; off; off >>= 1) {
                float od = __shfl_xor_sync(0xffffffffu, md, off);
                int   oi = __shfl_xor_sync(0xffffffffu, mi, off);
                if (pair_less(od, oi, md, mi)) { md = od; mi = oi; }
            }
            if (lane == 0) g_idx[q * KNB + k] = mi;
            r16 = md;
            if (hd == md && hi == mi) {
#pragma unroll
                for (int t = 0; t < KNB-1; ++t) { bd[t] = bd[t+1]; bi[t] = bi[t+1]; }
                bd[KNB-1] = 3.4e38f; bi[KNB-1] = 0x7fffffff;
                hd = bd[0]; hi = bi[0];
            }
        }

        // exactness: nearest possible unscanned point vs 16th distance
        float bmin = 1e30f;
        if (x0 > 0)        bmin = fminf(bmin, qx - (float)x0 * CELLSZ);
        if (x1 < GRID - 1) bmin = fminf(bmin, (float)(x1 + 1) * CELLSZ - qx);
        if (y0 > 0)        bmin = fminf(bmin, qy - (float)y0 * CELLSZ);
        if (y1 < GRID - 1) bmin = fminf(bmin, (float)(y1 + 1) * CELLSZ - qy);
        if (z0 > 0)        bmin = fminf(bmin, qz - (float)z0 * CELLSZ);
        if (z1 < GRID - 1) bmin = fminf(bmin, (float)(z1 + 1) * CELLSZ - qz);
        if (r16 <= bmin * bmin - 0.5f) break;
    }
}

// ---------------------------------------------------------------------------
// fp32 tiled GEMM (theta/phi/g and final W+residual)
// ---------------------------------------------------------------------------
__global__ __launch_bounds__(256) void gemm_kernel(
    const float* __restrict__ A, const float* __restrict__ B,
    const float* __restrict__ bias, const float* __restrict__ resid,
    float* __restrict__ outp, int Kd, int Nn)
{
    __shared__ __align__(16) float As[16][ASTRIDE];
    __shared__ __align__(16) float Bs[16][64];
    int tid = threadIdx.x;
    int tx = tid & 15, ty = tid >> 4;
    int m0 = blockIdx.y * 64, n0 = blockIdx.x * 64;

    float acc[4][4] = {};
    int arow = tid >> 2, akq = (tid & 3) * 4;
    int brow = tid >> 4, bc  = (tid & 15) * 4;

    for (int k0 = 0; k0 < Kd; k0 += 16) {
        float4 areg = *(const float4*)&A[(m0 + arow) * Kd + k0 + akq];
        float4 breg = *(const float4*)&B[(k0 + brow) * Nn + n0 + bc];
        __syncthreads();
        As[akq+0][arow] = areg.x; As[akq+1][arow] = areg.y;
        As[akq+2][arow] = areg.z; As[akq+3][arow] = areg.w;
        *(float4*)&Bs[brow][bc] = breg;
        __syncthreads();
#pragma unroll
        for (int kk = 0; kk < 16; ++kk) {
            float4 av = *(const float4*)&As[kk][ty * 4];
            float4 bv = *(const float4*)&Bs[kk][tx * 4];
            float aa[4] = {av.x, av.y, av.z, av.w};
            float bb[4] = {bv.x, bv.y, bv.z, bv.w};
#pragma unroll
            for (int i = 0; i < 4; ++i)
#pragma unroll
                for (int j = 0; j < 4; ++j)
                    acc[i][j] = fmaf(aa[i], bb[j], acc[i][j]);
        }
    }

    float4 bi4 = *(const float4*)&bias[n0 + tx * 4];
    float bb[4] = {bi4.x, bi4.y, bi4.z, bi4.w};
#pragma unroll
    for (int i = 0; i < 4; ++i) {
        int m = m0 + ty * 4 + i;
        float4 o;
        o.x = acc[i][0] + bb[0]; o.y = acc[i][1] + bb[1];
        o.z = acc[i][2] + bb[2]; o.w = acc[i][3] + bb[3];
        if (resid) {
            float4 r = *(const float4*)&resid[m * Nn + n0 + tx * 4];
            o.x += r.x; o.y += r.y; o.z += r.z; o.w += r.w;
        }
        *(float4*)&outp[m * Nn + n0 + tx * 4] = o;
    }
}

// ===========================================================================
// Fused attention via mma.sync bf16 (HMMA) — unchanged from round 3.
// ===========================================================================
#define OFF_JS   0
#define OFF_DC   512
#define OFF_W1   2048
#define OFF_H    6144
#define HSTR_B   528
#define OFF_W2   73728
#define WSTR_B   144
#define ATTN_SMEM 110592

__global__ __launch_bounds__(256, 2) void attn_kernel(
    const float* __restrict__ coords,
    const float* __restrict__ pw1, const float* __restrict__ pb1,
    const float* __restrict__ pw2, const float* __restrict__ pb2)
{
    extern __shared__ __align__(16) char sm[];
    int*    js  = (int*)(sm + OFF_JS);
    float*  dc0 = (float*)(sm + OFF_DC);
    float*  dc1 = dc0 + 128;
    float*  dc2 = dc0 + 256;
    float4* w1f = (float4*)(sm + OFF_W1);

    const int tid  = threadIdx.x;
    const int lane = tid & 31;
    const int wp   = tid >> 5;
    const int n0   = blockIdx.x * 8;

    if (tid < 128) {
        int p = tid >> 4, k = tid & 15;
        int n = n0 + p;
        int j = g_idx[n * KNB + k];
        js[tid] = j;
        dc0[tid] = coords[3*j+0] - coords[3*n+0];
        dc1[tid] = coords[3*j+1] - coords[3*n+1];
        dc2[tid] = coords[3*j+2] - coords[3*n+2];
    }
    w1f[tid] = make_float4(pw1[tid], pw1[CH + tid], pw1[2*CH + tid], pb1[tid]);
    __syncthreads();

    for (int it = tid; it < 128 * 128; it += 256) {
        int m = it >> 7, q = it & 127;
        float4 wa = w1f[2*q], wb = w1f[2*q + 1];
        float d0 = dc0[m], d1 = dc1[m], d2 = dc2[m];
        float h0 = fmaxf(fmaf(d0, wa.x, fmaf(d1, wa.y, fmaf(d2, wa.z, wa.w))), 0.f);
        float h1 = fmaxf(fmaf(d0, wb.x, fmaf(d1, wb.y, fmaf(d2, wb.z, wb.w))), 0.f);
        *(__nv_bfloat162*)(sm + OFF_H + m * HSTR_B + q * 4) = __floats2bfloat162_rn(h0, h1);
    }

    const uint32_t sbase = smem_u32(sm);
    const uint32_t aAddrBase = sbase + OFF_H +
        (uint32_t)(wp * 16 + (lane & 15)) * HSTR_B + (uint32_t)(lane >> 4) * 16;
    const uint32_t bAddrBase = sbase + OFF_W2 + (uint32_t)(lane & 15) * WSTR_B;

    const int r1 = lane >> 2;
    const int m1 = wp * 16 + r1, m2 = m1 + 8;
    const float inv = 0.0625f;

    for (int nc = 0; nc < 4; ++nc) {
        const int nbase = nc * 64;
        __syncthreads();
        for (int it = tid; it < 8192; it += 256) {
            int q = it & 31, k = it >> 5;
            float2 v = *(const float2*)&pw2[k * CH + nbase + 2 * q];
            *(__nv_bfloat162*)(sm + OFF_W2 + k * WSTR_B + q * 4) =
                __floats2bfloat162_rn(v.x, v.y);
        }
        __syncthreads();

        float acc[8][4];
#pragma unroll
        for (int t = 0; t < 8; ++t)
#pragma unroll
            for (int i = 0; i < 4; ++i) acc[t][i] = 0.f;

#pragma unroll 4
        for (int kt = 0; kt < 16; ++kt) {
            uint32_t a0, a1, a2, a3;
            asm volatile("ldmatrix.sync.aligned.m8n8.x4.shared.b16 {%0,%1,%2,%3}, [%4];"
                         : "=r"(a0), "=r"(a1), "=r"(a2), "=r"(a3)
                         : "r"(aAddrBase + (uint32_t)kt * 32));
#pragma unroll
            for (int t = 0; t < 8; ++t) {
                uint32_t b0, b1;
                asm volatile("ldmatrix.sync.aligned.m8n8.x2.trans.shared.b16 {%0,%1}, [%2];"
                             : "=r"(b0), "=r"(b1)
                             : "r"(bAddrBase + (uint32_t)kt * (16 * WSTR_B) + (uint32_t)t * 16));
                asm volatile("mma.sync.aligned.m16n8k16.row.col.f32.bf16.bf16.f32 "
                             "{%0,%1,%2,%3}, {%4,%5,%6,%7}, {%8,%9}, {%0,%1,%2,%3};"
                             : "+f"(acc[t][0]), "+f"(acc[t][1]), "+f"(acc[t][2]), "+f"(acc[t][3])
                             : "r"(a0), "r"(a1), "r"(a2), "r"(a3), "r"(b0), "r"(b1));
            }
        }

        const int j1 = js[m1], j2 = js[m2];
        const float* thp = g_theta + (size_t)(n0 + wp) * CH;
#pragma unroll
        for (int t = 0; t < 8; ++t) {
            int ca = nbase + t * 8 + 2 * (lane & 3);
            float2 th  = *(const float2*)&thp[ca];
            float2 b2  = *(const float2*)&pb2[ca];
            float2 p1  = *(const float2*)&g_phi[(size_t)j1 * CH + ca];
            float2 p2  = *(const float2*)&g_phi[(size_t)j2 * CH + ca];
            float2 gg1 = *(const float2*)&g_gf [(size_t)j1 * CH + ca];
            float2 gg2 = *(const float2*)&g_gf [(size_t)j2 * CH + ca];
            float pe00 = acc[t][0] + b2.x, pe01 = acc[t][1] + b2.y;
            float pe10 = acc[t][2] + b2.x, pe11 = acc[t][3] + b2.y;
            float v00 = fmaf(pe00, th.x - p1.x, pe00) * inv;
            float v01 = fmaf(pe01, th.y - p1.y, pe01) * inv;
            float v10 = fmaf(pe10, th.x - p2.x, pe10) * inv;
            float v11 = fmaf(pe11, th.y - p2.y, pe11) * inv;
            float mx = fmaxf(fmaxf(v00, v01), fmaxf(v10, v11));
#pragma unroll
            for (int off = 4; off <= 16; off <<= 1)
                mx = fmaxf(mx, __shfl_xor_sync(0xffffffffu, mx, off));
            float e00 = __expf(v00 - mx), e01 = __expf(v01 - mx);
            float e10 = __expf(v10 - mx), e11 = __expf(v11 - mx);
            float sa = e00 + e10, sb = e01 + e11;
            float ya = fmaf(e00, gg1.x, e10 * gg2.x);
            float yb = fmaf(e01, gg1.y, e11 * gg2.y);
#pragma unroll
            for (int off = 4; off <= 16; off <<= 1) {
                sa += __shfl_xor_sync(0xffffffffu, sa, off);
                sb += __shfl_xor_sync(0xffffffffu, sb, off);
                ya += __shfl_xor_sync(0xffffffffu, ya, off);
                yb += __shfl_xor_sync(0xffffffffu, yb, off);
            }
            if (lane < 4)
                *(float2*)&g_y[(size_t)(n0 + wp) * CH + ca] = make_float2(ya / sa, yb / sb);
        }
    }
}

// ---------------------------------------------------------------------------
extern "C" void kernel_launch(void* const* d_in, const int* in_sizes, int n_in,
                              void* d_out, int out_size)
{
    const float* coords  = (const float*)d_in[0];
    const float* feats   = (const float*)d_in[1];
    const float* theta_w = (const float*)d_in[2];
    const float* theta_b = (const float*)d_in[3];
    const float* phi_w   = (const float*)d_in[4];
    const float* phi_b   = (const float*)d_in[5];
    const float* g_w     = (const float*)d_in[6];
    const float* g_b     = (const float*)d_in[7];
    const float* pe1_w1  = (const float*)d_in[8];
    const float* pe1_b1  = (const float*)d_in[9];
    const float* pe1_w2  = (const float*)d_in[10];
    const float* pe1_b2  = (const float*)d_in[11];
    const float* W_w     = (const float*)d_in[12];
    const float* W_b     = (const float*)d_in[13];
    float* out = (float*)d_out;

    float *p_theta, *p_phi, *p_g, *p_y;
    cudaGetSymbolAddress((void**)&p_theta, g_theta);
    cudaGetSymbolAddress((void**)&p_phi,   g_phi);
    cudaGetSymbolAddress((void**)&p_g,     g_gf);
    cudaGetSymbolAddress((void**)&p_y,     g_y);

    cudaFuncSetAttribute((const void*)attn_kernel,
                         cudaFuncAttributeMaxDynamicSharedMemorySize, ATTN_SMEM);

    grid_zero_kernel<<<1, NCELLS>>>();
    grid_count_kernel<<<NPTS / 256, 256>>>(coords);
    grid_prefix_kernel<<<1, NCELLS>>>();
    grid_scatter_kernel<<<NPTS / 256, 256>>>(coords);
    knn_grid_kernel<<<NPTS / 8, 256>>>(coords);

    dim3 ggrid(CH / 64, NPTS / 64);
    gemm_kernel<<<ggrid, 256>>>(feats, theta_w, theta_b, nullptr, p_theta, CH, CH);
    gemm_kernel<<<ggrid, 256>>>(feats, phi_w,   phi_b,   nullptr, p_phi,   CH, CH);
    gemm_kernel<<<ggrid, 256>>>(feats, g_w,     g_b,     nullptr, p_g,     CH, CH);

    attn_kernel<<<NPTS / 8, 256, ATTN_SMEM>>>(coords, pe1_w1, pe1_b1, pe1_w2, pe1_b2);

    gemm_kernel<<<ggrid, 256>>>(p_y, W_w, W_b, feats, out, CH, CH);
}

// round 6
// speedup vs baseline: 3.4529x; 1.0789x over previous
#include <cuda_runtime.h>
#include <cuda_bf16.h>
#include <cstdint>

#define NPTS 8192
#define CH   256
#define KNB  16

#define GRID   8
#define NCELLS 512
#define CELLSZ 12.5f
#define INVCELL 0.08f

// scratch (device globals: no allocation allowed)
__device__ int   g_idx[NPTS * KNB];
__device__ float g_theta[NPTS * CH];
__device__ float g_phi[NPTS * CH];
__device__ float g_gf[NPTS * CH];
__device__ float g_y[NPTS * CH];
__device__ uint32_t g_w2pack[4 * 8192];   // bf16x2, smem image per 64-col chunk

__device__ int    g_cellCnt[NCELLS];
__device__ int    g_cellStart[NCELLS];
__device__ int    g_cellOffs[NCELLS];
__device__ float4 g_spts[NPTS];
__device__ int    g_sidx[NPTS];
__device__ int    g_pcell[NPTS];

__device__ __forceinline__ bool pair_less(float d1, int i1, float d2, int i2) {
    return d1 < d2 || (d1 == d2 && i1 < i2);
}

__device__ __forceinline__ int cell_of(float x) {
    int c = (int)(x * INVCELL);
    return c < 0 ? 0 : (c > GRID - 1 ? GRID - 1 : c);
}

__device__ __forceinline__ uint32_t smem_u32(const void* p) {
    uint32_t a;
    asm("{ .reg .u64 t; cvta.to.shared.u64 t, %1; cvt.u32.u64 %0, t; }" : "=r"(a) : "l"(p));
    return a;
}

__device__ __forceinline__ uint32_t f2tf(float v) {
    uint32_t r;
    asm("cvt.rna.tf32.f32 %0, %1;" : "=r"(r) : "f"(v));
    return r;
}

// ---------------------------------------------------------------------------
// Grid build
// ---------------------------------------------------------------------------
__global__ void grid_zero_kernel() {
    g_cellCnt[threadIdx.x] = 0;
}

__global__ void grid_count_kernel(const float* __restrict__ coords) {
    int i = blockIdx.x * 256 + threadIdx.x;
    float x = coords[3*i+0], y = coords[3*i+1], z = coords[3*i+2];
    int c = (cell_of(z) * GRID + cell_of(y)) * GRID + cell_of(x);
    g_pcell[i] = c;
    atomicAdd(&g_cellCnt[c], 1);
}

__global__ void grid_prefix_kernel() {
    __shared__ int tmp[NCELLS];
    int t = threadIdx.x;
    int v = g_cellCnt[t];
    tmp[t] = v;
    __syncthreads();
    for (int off = 1; off < NCELLS; off <<= 1) {
        int a = (t >= off) ? tmp[t - off] : 0;
        __syncthreads();
        tmp[t] += a;
        __syncthreads();
    }
    int excl = tmp[t] - v;
    g_cellStart[t] = excl;
    g_cellOffs[t]  = excl;
}

__global__ void grid_scatter_kernel(const float* __restrict__ coords) {
    int i = blockIdx.x * 256 + threadIdx.x;
    float x = coords[3*i+0], y = coords[3*i+1], z = coords[3*i+2];
    int c = g_pcell[i];
    int pos = atomicAdd(&g_cellOffs[c], 1);
    g_spts[pos] = make_float4(x, y, z, x*x + y*y + z*z);
    g_sidx[pos] = i;
}

// W2 prepack: bf16x2, per-chunk layout identical to attn smem image
__global__ void prep_w2_kernel(const float* __restrict__ pw2) {
    int idx = blockIdx.x * 256 + threadIdx.x;      // 32768
    int nc = idx >> 13, rem = idx & 8191;
    int q = rem & 31, k = rem >> 5;
    const float* p = pw2 + k * CH + nc * 64 + 2 * q;
    ((__nv_bfloat162*)g_w2pack)[idx] = __floats2bfloat162_rn(p[0], p[1]);
}

// ---------------------------------------------------------------------------
// Grid KNN (unchanged from round 5)
// ---------------------------------------------------------------------------
__global__ __launch_bounds__(256) void knn_grid_kernel(const float* __restrict__ coords) {
    int tid  = threadIdx.x;
    int lane = tid & 31;
    int q    = blockIdx.x * 8 + (tid >> 5);

    float qx = coords[3*q+0], qy = coords[3*q+1], qz = coords[3*q+2];
    float qsq = qx*qx + qy*qy + qz*qz;
    int cx = cell_of(qx), cy = cell_of(qy), cz = cell_of(qz);

    for (int R = 1; R <= GRID; ++R) {
        float bd[KNB]; int bi[KNB];
#pragma unroll
        for (int t = 0; t < KNB; ++t) { bd[t] = 3.4e38f; bi[t] = 0x7fffffff; }

        int x0 = max(cx - R, 0), x1 = min(cx + R, GRID - 1);
        int y0 = max(cy - R, 0), y1 = min(cy + R, GRID - 1);
        int z0 = max(cz - R, 0), z1 = min(cz + R, GRID - 1);

        for (int zz = z0; zz <= z1; ++zz)
        for (int yy = y0; yy <= y1; ++yy)
        for (int xx = x0; xx <= x1; ++xx) {
            int cell  = (zz * GRID + yy) * GRID + xx;
            int start = g_cellStart[cell];
            int cnt   = g_cellCnt[cell];
            for (int b = 0; b < cnt; b += 32) {
                int i = b + lane;
                if (i < cnt) {
                    float4 p = g_spts[start + i];
                    int j = g_sidx[start + i];
                    float d = qsq + p.w - 2.0f * (qx*p.x + qy*p.y + qz*p.z);
                    if (pair_less(d, j, bd[KNB-1], bi[KNB-1])) {
                        float cd = d; int ci = j;
#pragma unroll
                        for (int t = 0; t < KNB; ++t) {
                            bool sw = pair_less(cd, ci, bd[t], bi[t]);
                            float td = sw ? bd[t] : cd; int ti = sw ? bi[t] : ci;
                            bd[t] = sw ? cd : bd[t];   bi[t] = sw ? ci : bi[t];
                            cd = td; ci = ti;
                        }
                    }
                }
            }
        }

        float hd = bd[0]; int hi = bi[0];
        float r16 = 3.4e38f;
        for (int k = 0; k < KNB; ++k) {
            float md = hd; int mi = hi;
#pragma unroll
            for (int off = 16; off; off >>= 1) {
                float od = __shfl_xor_sync(0xffffffffu, md, off);
                int   oi = __shfl_xor_sync(0xffffffffu, mi, off);
                if (pair_less(od, oi, md, mi)) { md = od; mi = oi; }
            }
            if (lane == 0) g_idx[q * KNB + k] = mi;
            r16 = md;
            if (hd == md && hi == mi) {
#pragma unroll
                for (int t = 0; t < KNB-1; ++t) { bd[t] = bd[t+1]; bi[t] = bi[t+1]; }
                bd[KNB-1] = 3.4e38f; bi[KNB-1] = 0x7fffffff;
                hd = bd[0]; hi = bi[0];
            }
        }

        float bmin = 1e30f;
        if (x0 > 0)        bmin = fminf(bmin, qx - (float)x0 * CELLSZ);
        if (x1 < GRID - 1) bmin = fminf(bmin, (float)(x1 + 1) * CELLSZ - qx);
        if (y0 > 0)        bmin = fminf(bmin, qy - (float)y0 * CELLSZ);
        if (y1 < GRID - 1) bmin = fminf(bmin, (float)(y1 + 1) * CELLSZ - qy);
        if (z0 > 0)        bmin = fminf(bmin, qz - (float)z0 * CELLSZ);
        if (z1 < GRID - 1) bmin = fminf(bmin, (float)(z1 + 1) * CELLSZ - qz);
        if (r16 <= bmin * bmin - 0.5f) break;
    }
}

// ---------------------------------------------------------------------------
// 3xTF32 tensor-core GEMM: out[M,N] = A[M,256] @ B[256,N] + bias (+resid).
// Block 128x64, 8 warps (4m x 2n), warp tile 32x32, mma.m16n8k8.tf32.
// Split fp32 = tf32_hi + tf32_lo; passes hi*hi + hi*lo + lo*hi (fp32-class).
// A smem stride 20, B stride 72: conflict-free fragment LDS (verified maps).
// ---------------------------------------------------------------------------
#define ASTR 20
#define BSTR 72

__global__ __launch_bounds__(256) void gemm3x_kernel(
    const float* __restrict__ A, const float* __restrict__ B,
    const float* __restrict__ bias, const float* __restrict__ resid,
    float* __restrict__ outp, int Kd, int Nn)
{
    __shared__ __align__(16) float As[128 * ASTR];
    __shared__ __align__(16) float Bs[16 * BSTR];

    const int tid  = threadIdx.x;
    const int lane = tid & 31;
    const int w    = tid >> 5;
    const int wm   = w & 3, wn = w >> 2;
    const int m0 = blockIdx.y * 128, n0 = blockIdx.x * 64;

    const int lg = lane >> 2;      // group (row) 0..7
    const int lt = lane & 3;       // thread-in-group (col) 0..3

    float acc[2][4][4];
#pragma unroll
    for (int t = 0; t < 2; ++t)
#pragma unroll
        for (int u = 0; u < 4; ++u)
#pragma unroll
            for (int i = 0; i < 4; ++i) acc[t][u][i] = 0.f;

    const int arow = tid >> 1, abase = (tid & 1) * 8;
    const int bk = tid >> 4, bn4 = (tid & 15) * 4;

    for (int k0 = 0; k0 < Kd; k0 += 16) {
        float4 a0r = *(const float4*)&A[(m0 + arow) * Kd + k0 + abase];
        float4 a1r = *(const float4*)&A[(m0 + arow) * Kd + k0 + abase + 4];
        float4 b0r = *(const float4*)&B[(k0 + bk) * Nn + n0 + bn4];
        __syncthreads();
        *(float4*)&As[arow * ASTR + abase]     = a0r;
        *(float4*)&As[arow * ASTR + abase + 4] = a1r;
        *(float4*)&Bs[bk * BSTR + bn4]         = b0r;
        __syncthreads();

#pragma unroll
        for (int kk = 0; kk < 16; kk += 8) {
            uint32_t ah[2][4], al[2][4], bh[4][2], bl[4][2];
#pragma unroll
            for (int t = 0; t < 2; ++t) {
                int r0 = (wm * 32 + t * 16 + lg) * ASTR + kk + lt;
                float v0 = As[r0],            v1 = As[r0 + 8 * ASTR];
                float v2 = As[r0 + 4],        v3 = As[r0 + 8 * ASTR + 4];
                ah[t][0] = f2tf(v0); al[t][0] = f2tf(v0 - __uint_as_float(ah[t][0]));
                ah[t][1] = f2tf(v1); al[t][1] = f2tf(v1 - __uint_as_float(ah[t][1]));
                ah[t][2] = f2tf(v2); al[t][2] = f2tf(v2 - __uint_as_float(ah[t][2]));
                ah[t][3] = f2tf(v3); al[t][3] = f2tf(v3 - __uint_as_float(ah[t][3]));
            }
#pragma unroll
            for (int u = 0; u < 4; ++u) {
                int cb = wn * 32 + u * 8 + lg;
                float v0 = Bs[(kk + lt) * BSTR + cb];
                float v1 = Bs[(kk + 4 + lt) * BSTR + cb];
                bh[u][0] = f2tf(v0); bl[u][0] = f2tf(v0 - __uint_as_float(bh[u][0]));
                bh[u][1] = f2tf(v1); bl[u][1] = f2tf(v1 - __uint_as_float(bh[u][1]));
            }
#pragma unroll
            for (int t = 0; t < 2; ++t)
#pragma unroll
                for (int u = 0; u < 4; ++u) {
#define MMA_TF32(A0,A1,A2,A3,B0,B1) \
    asm volatile("mma.sync.aligned.m16n8k8.row.col.f32.tf32.tf32.f32 " \
        "{%0,%1,%2,%3}, {%4,%5,%6,%7}, {%8,%9}, {%0,%1,%2,%3};" \
        : "+f"(acc[t][u][0]), "+f"(acc[t][u][1]), "+f"(acc[t][u][2]), "+f"(acc[t][u][3]) \
        : "r"(A0), "r"(A1), "r"(A2), "r"(A3), "r"(B0), "r"(B1))
                    MMA_TF32(ah[t][0], ah[t][1], ah[t][2], ah[t][3], bh[u][0], bh[u][1]);
                    MMA_TF32(ah[t][0], ah[t][1], ah[t][2], ah[t][3], bl[u][0], bl[u][1]);
                    MMA_TF32(al[t][0], al[t][1], al[t][2], al[t][3], bh[u][0], bh[u][1]);
#undef MMA_TF32
                }
        }
    }

#pragma unroll
    for (int t = 0; t < 2; ++t) {
        int r0 = m0 + wm * 32 + t * 16 + lg;
#pragma unroll
        for (int u = 0; u < 4; ++u) {
            int nb = n0 + wn * 32 + u * 8 + 2 * lt;
            float2 b = *(const float2*)&bias[nb];
            float2 o0 = make_float2(acc[t][u][0] + b.x, acc[t][u][1] + b.y);
            float2 o1 = make_float2(acc[t][u][2] + b.x, acc[t][u][3] + b.y);
            if (resid) {
                float2 r0v = *(const float2*)&resid[(size_t)r0 * Nn + nb];
                float2 r1v = *(const float2*)&resid[(size_t)(r0 + 8) * Nn + nb];
                o0.x += r0v.x; o0.y += r0v.y;
                o1.x += r1v.x; o1.y += r1v.y;
            }
            *(float2*)&outp[(size_t)r0 * Nn + nb]       = o0;
            *(float2*)&outp[(size_t)(r0 + 8) * Nn + nb] = o1;
        }
    }
}

// ===========================================================================
// Fused attention via mma.sync bf16 (HMMA); W2 staged from prepacked bf16.
// ===========================================================================
#define OFF_JS   0
#define OFF_DC   512
#define OFF_W1   2048
#define OFF_H    6144
#define HSTR_B   528
#define OFF_W2   73728
#define WSTR_B   144
#define ATTN_SMEM 110592

__global__ __launch_bounds__(256, 2) void attn_kernel(
    const float* __restrict__ coords,
    const float* __restrict__ pw1, const float* __restrict__ pb1,
    const float* __restrict__ pb2)
{
    extern __shared__ __align__(16) char sm[];
    int*    js  = (int*)(sm + OFF_JS);
    float*  dc0 = (float*)(sm + OFF_DC);
    float*  dc1 = dc0 + 128;
    float*  dc2 = dc0 + 256;
    float4* w1f = (float4*)(sm + OFF_W1);

    const int tid  = threadIdx.x;
    const int lane = tid & 31;
    const int wp   = tid >> 5;
    const int n0   = blockIdx.x * 8;

    if (tid < 128) {
        int p = tid >> 4, k = tid & 15;
        int n = n0 + p;
        int j = g_idx[n * KNB + k];
        js[tid] = j;
        dc0[tid] = coords[3*j+0] - coords[3*n+0];
        dc1[tid] = coords[3*j+1] - coords[3*n+1];
        dc2[tid] = coords[3*j+2] - coords[3*n+2];
    }
    w1f[tid] = make_float4(pw1[tid], pw1[CH + tid], pw1[2*CH + tid], pb1[tid]);
    __syncthreads();

    for (int it = tid; it < 128 * 128; it += 256) {
        int m = it >> 7, q = it & 127;
        float4 wa = w1f[2*q], wb = w1f[2*q + 1];
        float d0 = dc0[m], d1 = dc1[m], d2 = dc2[m];
        float h0 = fmaxf(fmaf(d0, wa.x, fmaf(d1, wa.y, fmaf(d2, wa.z, wa.w))), 0.f);
        float h1 = fmaxf(fmaf(d0, wb.x, fmaf(d1, wb.y, fmaf(d2, wb.z, wb.w))), 0.f);
        *(__nv_bfloat162*)(sm + OFF_H + m * HSTR_B + q * 4) = __floats2bfloat162_rn(h0, h1);
    }

    const uint32_t sbase = smem_u32(sm);
    const uint32_t aAddrBase = sbase + OFF_H +
        (uint32_t)(wp * 16 + (lane & 15)) * HSTR_B + (uint32_t)(lane >> 4) * 16;
    const uint32_t bAddrBase = sbase + OFF_W2 + (uint32_t)(lane & 15) * WSTR_B;

    const int r1 = lane >> 2;
    const int m1 = wp * 16 + r1, m2 = m1 + 8;
    const float inv = 0.0625f;

    for (int nc = 0; nc < 4; ++nc) {
        const int nbase = nc * 64;
        __syncthreads();
        // stage prepacked W2 chunk: pure 16B copy
        for (int it = tid; it < 2048; it += 256) {
            int k = it >> 3, q4 = (it & 7) * 4;
            uint4 v = ((const uint4*)g_w2pack)[nc * 2048 + it];
            *(uint4*)(sm + OFF_W2 + k * WSTR_B + q4 * 4) = v;
        }
        __syncthreads();

        float acc[8][4];
#pragma unroll
        for (int t = 0; t < 8; ++t)
#pragma unroll
            for (int i = 0; i < 4; ++i) acc[t][i] = 0.f;

#pragma unroll 4
        for (int kt = 0; kt < 16; ++kt) {
            uint32_t a0, a1, a2, a3;
            asm volatile("ldmatrix.sync.aligned.m8n8.x4.shared.b16 {%0,%1,%2,%3}, [%4];"
                         : "=r"(a0), "=r"(a1), "=r"(a2), "=r"(a3)
                         : "r"(aAddrBase + (uint32_t)kt * 32));
#pragma unroll
            for (int t = 0; t < 8; ++t) {
                uint32_t b0, b1;
                asm volatile("ldmatrix.sync.aligned.m8n8.x2.trans.shared.b16 {%0,%1}, [%2];"
                             : "=r"(b0), "=r"(b1)
                             : "r"(bAddrBase + (uint32_t)kt * (16 * WSTR_B) + (uint32_t)t * 16));
                asm volatile("mma.sync.aligned.m16n8k16.row.col.f32.bf16.bf16.f32 "
                             "{%0,%1,%2,%3}, {%4,%5,%6,%7}, {%8,%9}, {%0,%1,%2,%3};"
                             : "+f"(acc[t][0]), "+f"(acc[t][1]), "+f"(acc[t][2]), "+f"(acc[t][3])
                             : "r"(a0), "r"(a1), "r"(a2), "r"(a3), "r"(b0), "r"(b1));
            }
        }

        const int j1 = js[m1], j2 = js[m2];
        const float* thp = g_theta + (size_t)(n0 + wp) * CH;
#pragma unroll
        for (int t = 0; t < 8; ++t) {
            int ca = nbase + t * 8 + 2 * (lane & 3);
            float2 th  = *(const float2*)&thp[ca];
            float2 b2  = *(const float2*)&pb2[ca];
            float2 p1  = *(const float2*)&g_phi[(size_t)j1 * CH + ca];
            float2 p2  = *(const float2*)&g_phi[(size_t)j2 * CH + ca];
            float2 gg1 = *(const float2*)&g_gf [(size_t)j1 * CH + ca];
            float2 gg2 = *(const float2*)&g_gf [(size_t)j2 * CH + ca];
            float pe00 = acc[t][0] + b2.x, pe01 = acc[t][1] + b2.y;
            float pe10 = acc[t][2] + b2.x, pe11 = acc[t][3] + b2.y;
            float v00 = fmaf(pe00, th.x - p1.x, pe00) * inv;
            float v01 = fmaf(pe01, th.y - p1.y, pe01) * inv;
            float v10 = fmaf(pe10, th.x - p2.x, pe10) * inv;
            float v11 = fmaf(pe11, th.y - p2.y, pe11) * inv;
            float mx = fmaxf(fmaxf(v00, v01), fmaxf(v10, v11));
#pragma unroll
            for (int off = 4; off <= 16; off <<= 1)
                mx = fmaxf(mx, __shfl_xor_sync(0xffffffffu, mx, off));
            float e00 = __expf(v00 - mx), e01 = __expf(v01 - mx);
            float e10 = __expf(v10 - mx), e11 = __expf(v11 - mx);
            float sa = e00 + e10, sb = e01 + e11;
            float ya = fmaf(e00, gg1.x, e10 * gg2.x);
            float yb = fmaf(e01, gg1.y, e11 * gg2.y);
#pragma unroll
            for (int off = 4; off <= 16; off <<= 1) {
                sa += __shfl_xor_sync(0xffffffffu, sa, off);
                sb += __shfl_xor_sync(0xffffffffu, sb, off);
                ya += __shfl_xor_sync(0xffffffffu, ya, off);
                yb += __shfl_xor_sync(0xffffffffu, yb, off);
            }
            if (lane < 4)
                *(float2*)&g_y[(size_t)(n0 + wp) * CH + ca] = make_float2(ya / sa, yb / sb);
        }
    }
}

// ---------------------------------------------------------------------------
extern "C" void kernel_launch(void* const* d_in, const int* in_sizes, int n_in,
                              void* d_out, int out_size)
{
    const float* coords  = (const float*)d_in[0];
    const float* feats   = (const float*)d_in[1];
    const float* theta_w = (const float*)d_in[2];
    const float* theta_b = (const float*)d_in[3];
    const float* phi_w   = (const float*)d_in[4];
    const float* phi_b   = (const float*)d_in[5];
    const float* g_w     = (const float*)d_in[6];
    const float* g_b     = (const float*)d_in[7];
    const float* pe1_w1  = (const float*)d_in[8];
    const float* pe1_b1  = (const float*)d_in[9];
    const float* pe1_w2  = (const float*)d_in[10];
    const float* pe1_b2  = (const float*)d_in[11];
    const float* W_w     = (const float*)d_in[12];
    const float* W_b     = (const float*)d_in[13];
    float* out = (float*)d_out;

    float *p_theta, *p_phi, *p_g, *p_y;
    cudaGetSymbolAddress((void**)&p_theta, g_theta);
    cudaGetSymbolAddress((void**)&p_phi,   g_phi);
    cudaGetSymbolAddress((void**)&p_g,     g_gf);
    cudaGetSymbolAddress((void**)&p_y,     g_y);

    cudaFuncSetAttribute((const void*)attn_kernel,
                         cudaFuncAttributeMaxDynamicSharedMemorySize, ATTN_SMEM);

    grid_zero_kernel<<<1, NCELLS>>>();
    grid_count_kernel<<<NPTS / 256, 256>>>(coords);
    prep_w2_kernel<<<128, 256>>>(pe1_w2);
    grid_prefix_kernel<<<1, NCELLS>>>();
    grid_scatter_kernel<<<NPTS / 256, 256>>>(coords);
    knn_grid_kernel<<<NPTS / 8, 256>>>(coords);

    dim3 ggrid(CH / 64, NPTS / 128);
    gemm3x_kernel<<<ggrid, 256>>>(feats, theta_w, theta_b, nullptr, p_theta, CH, CH);
    gemm3x_kernel<<<ggrid, 256>>>(feats, phi_w,   phi_b,   nullptr, p_phi,   CH, CH);
    gemm3x_kernel<<<ggrid, 256>>>(feats, g_w,     g_b,     nullptr, p_g,     CH, CH);

    attn_kernel<<<NPTS / 8, 256, ATTN_SMEM>>>(coords, pe1_w1, pe1_b1, pe1_b2);

    gemm3x_kernel<<<ggrid, 256>>>(p_y, W_w, W_b, feats, out, CH, CH);
}

// round 7
// speedup vs baseline: 4.3516x; 1.2603x over previous
#include <cuda_runtime.h>
#include <cuda_bf16.h>
#include <cstdint>

#define NPTS 8192
#define CH   256
#define KNB  16

#define GRID   8
#define NCELLS 512
#define CELLSZ 12.5f
#define INVCELL 0.08f

// scratch (device globals: no allocation allowed)
__device__ int   g_idx[NPTS * KNB];
__device__ float g_theta[NPTS * CH];
__device__ float g_phi[NPTS * CH];
__device__ float g_gf[NPTS * CH];
__device__ uint32_t g_w2pack[4 * 8192];        // attn W2, bf16x2 smem image
__device__ uint32_t g_fpack[NPTS * 256];       // feats,  (hi,lo) bf16 words
__device__ uint32_t g_ypack[NPTS * 256];       // y,      (hi,lo) bf16 words
__device__ uint32_t g_wpack[4 * 2 * 4 * 512 * 32];  // weights [wsel][plane][nc][512][32]

__device__ int2   g_cellSC[NCELLS];    // (start, count)
__device__ int    g_cellCnt[NCELLS];
__device__ int    g_cellOffs[NCELLS];
__device__ float4 g_spts[NPTS];
__device__ int    g_sidx[NPTS];
__device__ int    g_pcell[NPTS];

__device__ __forceinline__ bool pair_less(float d1, int i1, float d2, int i2) {
    return d1 < d2 || (d1 == d2 && i1 < i2);
}

__device__ __forceinline__ int cell_of(float x) {
    int c = (int)(x * INVCELL);
    return c < 0 ? 0 : (c > GRID - 1 ? GRID - 1 : c);
}

__device__ __forceinline__ uint32_t smem_u32(const void* p) {
    uint32_t a;
    asm("{ .reg .u64 t; cvta.to.shared.u64 t, %1; cvt.u32.u64 %0, t; }" : "=r"(a) : "l"(p));
    return a;
}

// fp32 -> (bf16 hi | bf16 lo << 16)
__device__ __forceinline__ uint32_t splitw(float v) {
    __nv_bfloat16 h = __float2bfloat16(v);
    float l = v - __bfloat162float(h);
    __nv_bfloat16 lo = __float2bfloat16(l);
    return (uint32_t)__bfloat16_as_ushort(h) | ((uint32_t)__bfloat16_as_ushort(lo) << 16);
}

// ---------------------------------------------------------------------------
// Grid build + prepack
// ---------------------------------------------------------------------------
__global__ void grid_zero_kernel() {
    g_cellCnt[threadIdx.x] = 0;
}

__global__ void grid_count_kernel(const float* __restrict__ coords) {
    int i = blockIdx.x * 256 + threadIdx.x;
    float x = coords[3*i+0], y = coords[3*i+1], z = coords[3*i+2];
    int c = (cell_of(z) * GRID + cell_of(y)) * GRID + cell_of(x);
    g_pcell[i] = c;
    atomicAdd(&g_cellCnt[c], 1);
}

__global__ void grid_prefix_kernel() {
    __shared__ int tmp[NCELLS];
    int t = threadIdx.x;
    int v = g_cellCnt[t];
    tmp[t] = v;
    __syncthreads();
    for (int off = 1; off < NCELLS; off <<= 1) {
        int a = (t >= off) ? tmp[t - off] : 0;
        __syncthreads();
        tmp[t] += a;
        __syncthreads();
    }
    int excl = tmp[t] - v;
    g_cellSC[t]   = make_int2(excl, v);
    g_cellOffs[t] = excl;
}

__global__ void grid_scatter_kernel(const float* __restrict__ coords) {
    int i = blockIdx.x * 256 + threadIdx.x;
    float x = coords[3*i+0], y = coords[3*i+1], z = coords[3*i+2];
    int c = g_pcell[i];
    int pos = atomicAdd(&g_cellOffs[c], 1);
    g_spts[pos] = make_float4(x, y, z, x*x + y*y + z*z);
    g_sidx[pos] = i;
}

// attn W2 prepack (bf16x2, smem image per 64-col chunk)
__global__ void prep_w2_kernel(const float* __restrict__ pw2) {
    int idx = blockIdx.x * 256 + threadIdx.x;      // 32768
    int nc = idx >> 13, rem = idx & 8191;
    int q = rem & 31, k = rem >> 5;
    const float* p = pw2 + k * CH + nc * 64 + 2 * q;
    ((__nv_bfloat162*)g_w2pack)[idx] = __floats2bfloat162_rn(p[0], p[1]);
}

// feats -> (hi,lo) packed words
__global__ void prep_feats_kernel(const float* __restrict__ feats) {
    int t = blockIdx.x * 256 + threadIdx.x;        // 524288
    int row = t >> 6, q4 = (t & 63) * 4;
    float4 v = *(const float4*)&feats[row * 256 + q4];
    uint4 o;
    o.x = splitw(v.x); o.y = splitw(v.y); o.z = splitw(v.z); o.w = splitw(v.w);
    *(uint4*)&g_fpack[row * 256 + q4] = o;
}

// weights -> two-plane packed: [wsel][plane][nc][512 rows][32 words]
__global__ void prep_wts_kernel(const float* __restrict__ w0, const float* __restrict__ w1,
                                const float* __restrict__ w2, const float* __restrict__ w3)
{
    int idx = blockIdx.x * 256 + threadIdx.x;      // 524288
    int wsel  = idx >> 17;
    int plane = (idx >> 16) & 1;
    int nc    = (idx >> 14) & 3;
    int row   = (idx >> 5) & 511;
    int wq    = idx & 31;
    int k = row >> 1;
    int n = nc * 64 + wq * 2;
    const float* W = wsel == 0 ? w0 : (wsel == 1 ? w1 : (wsel == 2 ? w2 : w3));
    float v0 = W[k * 256 + n], v1 = W[k * 256 + n + 1];
    uint16_t a, b;
    if (plane == 0) {
        a = __bfloat16_as_ushort(__float2bfloat16(v0));
        b = __bfloat16_as_ushort(__float2bfloat16(v1));
    } else {
        a = __bfloat16_as_ushort(__float2bfloat16(v0 - __bfloat162float(__float2bfloat16(v0))));
        b = __bfloat16_as_ushort(__float2bfloat16(v1 - __bfloat162float(__float2bfloat16(v1))));
    }
    g_wpack[idx] = (uint32_t)a | ((uint32_t)b << 16);
}

// ---------------------------------------------------------------------------
// Grid KNN: descriptor prefetch (32-wide) + compacted candidate stream.
// ---------------------------------------------------------------------------
__global__ __launch_bounds__(256) void knn_grid_kernel(const float* __restrict__ coords) {
    int tid  = threadIdx.x;
    int lane = tid & 31;
    int q    = blockIdx.x * 8 + (tid >> 5);

    float qx = coords[3*q+0], qy = coords[3*q+1], qz = coords[3*q+2];
    float qsq = qx*qx + qy*qy + qz*qz;
    int cx = cell_of(qx), cy = cell_of(qy), cz = cell_of(qz);

    for (int R = 1; R <= GRID; ++R) {
        float bd[KNB]; int bi[KNB];
#pragma unroll
        for (int t = 0; t < KNB; ++t) { bd[t] = 3.4e38f; bi[t] = 0x7fffffff; }

        int x0 = max(cx - R, 0), x1 = min(cx + R, GRID - 1);
        int y0 = max(cy - R, 0), y1 = min(cy + R, GRID - 1);
        int z0 = max(cz - R, 0), z1 = min(cz + R, GRID - 1);
        int nx = x1 - x0 + 1, ny = y1 - y0 + 1, nz = z1 - z0 + 1;
        int nxy = nx * ny, ncell = nxy * nz;

        for (int g0 = 0; g0 < ncell; g0 += 32) {
            int ci = g0 + lane;
            int st = 0, cnt = 0;
            if (ci < ncell) {
                int zz = z0 + ci / nxy;
                int r2 = ci % nxy;
                int yy = y0 + r2 / nx;
                int xx = x0 + r2 % nx;
                int2 sc = g_cellSC[(zz * GRID + yy) * GRID + xx];
                st = sc.x; cnt = sc.y;
            }
            int cum = cnt;
#pragma unroll
            for (int off = 1; off < 32; off <<= 1) {
                int v = __shfl_up_sync(0xffffffffu, cum, off);
                if (lane >= off) cum += v;
            }
            int total = __shfl_sync(0xffffffffu, cum, 31);
            int excl = cum - cnt;

            for (int base = 0; base < total; base += 32) {
                int pos = base + lane;
                int c = 0;
#pragma unroll
                for (int step = 16; step; step >>= 1) {
                    int nc2 = c + step;
                    int v = __shfl_sync(0xffffffffu, cum, (nc2 - 1) & 31);
                    if (nc2 <= 32 && v <= pos) c = nc2;
                }
                int stc = __shfl_sync(0xffffffffu, st,   c & 31);
                int exc = __shfl_sync(0xffffffffu, excl, c & 31);
                if (pos < total) {
                    int gi = stc + (pos - exc);
                    float4 p = g_spts[gi];
                    int j = g_sidx[gi];
                    float d = qsq + p.w - 2.0f * (qx*p.x + qy*p.y + qz*p.z);
                    if (pair_less(d, j, bd[KNB-1], bi[KNB-1])) {
                        float cd = d; int ci2 = j;
#pragma unroll
                        for (int t = 0; t < KNB; ++t) {
                            bool sw = pair_less(cd, ci2, bd[t], bi[t]);
                            float td = sw ? bd[t] : cd; int ti = sw ? bi[t] : ci2;
                            bd[t] = sw ? cd : bd[t];   bi[t] = sw ? ci2 : bi[t];
                            cd = td; ci2 = ti;
                        }
                    }
                }
            }
        }

        float hd = bd[0]; int hi = bi[0];
        float r16 = 3.4e38f;
        for (int k = 0; k < KNB; ++k) {
            float md = hd; int mi = hi;
#pragma unroll
            for (int off = 16; off; off >>= 1) {
                float od = __shfl_xor_sync(0xffffffffu, md, off);
                int   oi = __shfl_xor_sync(0xffffffffu, mi, off);
                if (pair_less(od, oi, md, mi)) { md = od; mi = oi; }
            }
            if (lane == 0) g_idx[q * KNB + k] = mi;
            r16 = md;
            if (hd == md && hi == mi) {
#pragma unroll
                for (int t = 0; t < KNB-1; ++t) { bd[t] = bd[t+1]; bi[t] = bi[t+1]; }
                bd[KNB-1] = 3.4e38f; bi[KNB-1] = 0x7fffffff;
                hd = bd[0]; hi = bi[0];
            }
        }

        float bmin = 1e30f;
        if (x0 > 0)        bmin = fminf(bmin, qx - (float)x0 * CELLSZ);
        if (x1 < GRID - 1) bmin = fminf(bmin, (float)(x1 + 1) * CELLSZ - qx);
        if (y0 > 0)        bmin = fminf(bmin, qy - (float)y0 * CELLSZ);
        if (y1 < GRID - 1) bmin = fminf(bmin, (float)(y1 + 1) * CELLSZ - qy);
        if (z0 > 0)        bmin = fminf(bmin, qz - (float)z0 * CELLSZ);
        if (z1 < GRID - 1) bmin = fminf(bmin, (float)(z1 + 1) * CELLSZ - qz);
        if (r16 <= bmin * bmin - 0.5f) break;
    }
}

// ---------------------------------------------------------------------------
// Split-bf16 tensor GEMM: out[M,256] = A[M,256] @ W[256,256] + bias (+resid).
// A packed (hi,lo) along k' (K'=512); B two planes (hi, lo), rows duplicated,
// so plane passes accumulate (ah+al)*(bh+bl). Block 128x64, 8 warps (4m x 2n),
// ldmatrix + mma.m16n8k16.bf16, smem stride 144B conflict-free.
// Launch A: grid (4*nW, 64); wsel = blockIdx.x>>2 selects bias/out.
// ---------------------------------------------------------------------------
#define GSTR 36   // words per smem row (72 bf16 = 144B)

__global__ __launch_bounds__(256) void gemmsp_kernel(
    const uint32_t* __restrict__ Ap, const uint32_t* __restrict__ Bp,
    const float* __restrict__ bias0, const float* __restrict__ bias1,
    const float* __restrict__ bias2,
    float* __restrict__ out0, float* __restrict__ out1, float* __restrict__ out2,
    const float* __restrict__ resid)
{
    __shared__ __align__(16) uint32_t As[128 * GSTR];
    __shared__ __align__(16) uint32_t Bs[64 * GSTR];

    const int tid = threadIdx.x, lane = tid & 31, w = tid >> 5;
    const int wm = w & 3, wn = w >> 2;
    const int m0 = blockIdx.y * 128;
    const int nc = blockIdx.x & 3;
    const int wsel = blockIdx.x >> 2;
    const float* bias = wsel == 0 ? bias0 : (wsel == 1 ? bias1 : bias2);
    float* outp = wsel == 0 ? out0 : (wsel == 1 ? out1 : out2);

    float acc[2][4][4];
#pragma unroll
    for (int t = 0; t < 2; ++t)
#pragma unroll
        for (int u = 0; u < 4; ++u)
#pragma unroll
            for (int i = 0; i < 4; ++i) acc[t][u][i] = 0.f;

    uint4 aR[4], bR[2];
    const int arow4 = tid >> 3, awq = (tid & 7) * 4;   // +32 rows per u-step

#define LD_A(c) { \
    _Pragma("unroll") \
    for (int u2 = 0; u2 < 4; ++u2) \
        aR[u2] = *(const uint4*)&Ap[(size_t)(m0 + arow4 + u2 * 32) * 256 + (c) * 32 + awq]; }
#define LD_B(c, pl) { \
    _Pragma("unroll") \
    for (int u2 = 0; u2 < 2; ++u2) \
        bR[u2] = *(const uint4*)&Bp[((((size_t)wsel * 2 + (pl)) * 4 + nc) * 512 + (size_t)(c) * 64 + arow4 + u2 * 32) * 32 + awq]; }

    LD_A(0); LD_B(0, 0);

    const uint32_t smA = smem_u32(As), smB = smem_u32(Bs);
    const uint32_t aBase = smA + (uint32_t)((wm * 32 + (lane & 15)) * 144 + (lane >> 4) * 16);
    const uint32_t bBase = smB + (uint32_t)((lane & 15) * 144 + wn * 64);

    for (int s = 0; s < 16; ++s) {
        const int plane = s & 1;
        __syncthreads();
        if (plane == 0) {
#pragma unroll
            for (int u2 = 0; u2 < 4; ++u2)
                *(uint4*)&As[(arow4 + u2 * 32) * GSTR + awq] = aR[u2];
        }
#pragma unroll
        for (int u2 = 0; u2 < 2; ++u2)
            *(uint4*)&Bs[(arow4 + u2 * 32) * GSTR + awq] = bR[u2];
        __syncthreads();

        if (s < 15) {
            const int c2 = (s + 1) >> 1, p2 = (s + 1) & 1;
            if (p2 == 0) LD_A(c2);
            LD_B(c2, p2);
        }

#pragma unroll
        for (int ks = 0; ks < 4; ++ks) {
            uint32_t a[2][4];
#pragma unroll
            for (int t = 0; t < 2; ++t)
                asm volatile("ldmatrix.sync.aligned.m8n8.x4.shared.b16 {%0,%1,%2,%3}, [%4];"
                             : "=r"(a[t][0]), "=r"(a[t][1]), "=r"(a[t][2]), "=r"(a[t][3])
                             : "r"(aBase + (uint32_t)(t * 16 * 144 + ks * 32)));
#pragma unroll
            for (int u = 0; u < 4; ++u) {
                uint32_t b0, b1;
                asm volatile("ldmatrix.sync.aligned.m8n8.x2.trans.shared.b16 {%0,%1}, [%2];"
                             : "=r"(b0), "=r"(b1)
                             : "r"(bBase + (uint32_t)(ks * 16 * 144 + u * 16)));
#pragma unroll
                for (int t = 0; t < 2; ++t)
                    asm volatile("mma.sync.aligned.m16n8k16.row.col.f32.bf16.bf16.f32 "
                                 "{%0,%1,%2,%3}, {%4,%5,%6,%7}, {%8,%9}, {%0,%1,%2,%3};"
                                 : "+f"(acc[t][u][0]), "+f"(acc[t][u][1]),
                                   "+f"(acc[t][u][2]), "+f"(acc[t][u][3])
                                 : "r"(a[t][0]), "r"(a[t][1]), "r"(a[t][2]), "r"(a[t][3]),
                                   "r"(b0), "r"(b1));
            }
        }
    }

#pragma unroll
    for (int t = 0; t < 2; ++t) {
        int r0 = m0 + wm * 32 + t * 16 + (lane >> 2);
#pragma unroll
        for (int u = 0; u < 4; ++u) {
            int nb = nc * 64 + wn * 32 + u * 8 + 2 * (lane & 3);
            float2 b = *(const float2*)&bias[nb];
            float2 o0 = make_float2(acc[t][u][0] + b.x, acc[t][u][1] + b.y);
            float2 o1 = make_float2(acc[t][u][2] + b.x, acc[t][u][3] + b.y);
            if (resid) {
                float2 ra = *(const float2*)&resid[(size_t)r0 * 256 + nb];
                float2 rb = *(const float2*)&resid[(size_t)(r0 + 8) * 256 + nb];
                o0.x += ra.x; o0.y += ra.y; o1.x += rb.x; o1.y += rb.y;
            }
            *(float2*)&outp[(size_t)r0 * 256 + nb]       = o0;
            *(float2*)&outp[(size_t)(r0 + 8) * 256 + nb] = o1;
        }
    }
}

// ===========================================================================
// Fused attention via mma.sync bf16 (HMMA); y written in packed hi/lo form.
// ===========================================================================
#define OFF_JS   0
#define OFF_DC   512
#define OFF_W1   2048
#define OFF_H    6144
#define HSTR_B   528
#define OFF_W2   73728
#define WSTR_B   144
#define ATTN_SMEM 110592

__global__ __launch_bounds__(256, 2) void attn_kernel(
    const float* __restrict__ coords,
    const float* __restrict__ pw1, const float* __restrict__ pb1,
    const float* __restrict__ pb2)
{
    extern __shared__ __align__(16) char sm[];
    int*    js  = (int*)(sm + OFF_JS);
    float*  dc0 = (float*)(sm + OFF_DC);
    float*  dc1 = dc0 + 128;
    float*  dc2 = dc0 + 256;
    float4* w1f = (float4*)(sm + OFF_W1);

    const int tid  = threadIdx.x;
    const int lane = tid & 31;
    const int wp   = tid >> 5;
    const int n0   = blockIdx.x * 8;

    if (tid < 128) {
        int p = tid >> 4, k = tid & 15;
        int n = n0 + p;
        int j = g_idx[n * KNB + k];
        js[tid] = j;
        dc0[tid] = coords[3*j+0] - coords[3*n+0];
        dc1[tid] = coords[3*j+1] - coords[3*n+1];
        dc2[tid] = coords[3*j+2] - coords[3*n+2];
    }
    w1f[tid] = make_float4(pw1[tid], pw1[CH + tid], pw1[2*CH + tid], pb1[tid]);
    __syncthreads();

    for (int it = tid; it < 128 * 128; it += 256) {
        int m = it >> 7, q = it & 127;
        float4 wa = w1f[2*q], wb = w1f[2*q + 1];
        float d0 = dc0[m], d1 = dc1[m], d2 = dc2[m];
        float h0 = fmaxf(fmaf(d0, wa.x, fmaf(d1, wa.y, fmaf(d2, wa.z, wa.w))), 0.f);
        float h1 = fmaxf(fmaf(d0, wb.x, fmaf(d1, wb.y, fmaf(d2, wb.z, wb.w))), 0.f);
        *(__nv_bfloat162*)(sm + OFF_H + m * HSTR_B + q * 4) = __floats2bfloat162_rn(h0, h1);
    }

    const uint32_t sbase = smem_u32(sm);
    const uint32_t aAddrBase = sbase + OFF_H +
        (uint32_t)(wp * 16 + (lane & 15)) * HSTR_B + (uint32_t)(lane >> 4) * 16;
    const uint32_t bAddrBase = sbase + OFF_W2 + (uint32_t)(lane & 15) * WSTR_B;

    const int r1 = lane >> 2;
    const int m1 = wp * 16 + r1, m2 = m1 + 8;
    const float inv = 0.0625f;

    for (int nc = 0; nc < 4; ++nc) {
        const int nbase = nc * 64;
        __syncthreads();
        for (int it = tid; it < 2048; it += 256) {
            int k = it >> 3, q4 = (it & 7) * 4;
            uint4 v = ((const uint4*)g_w2pack)[nc * 2048 + it];
            *(uint4*)(sm + OFF_W2 + k * WSTR_B + q4 * 4) = v;
        }
        __syncthreads();

        float acc[8][4];
#pragma unroll
        for (int t = 0; t < 8; ++t)
#pragma unroll
            for (int i = 0; i < 4; ++i) acc[t][i] = 0.f;

#pragma unroll 4
        for (int kt = 0; kt < 16; ++kt) {
            uint32_t a0, a1, a2, a3;
            asm volatile("ldmatrix.sync.aligned.m8n8.x4.shared.b16 {%0,%1,%2,%3}, [%4];"
                         : "=r"(a0), "=r"(a1), "=r"(a2), "=r"(a3)
                         : "r"(aAddrBase + (uint32_t)kt * 32));
#pragma unroll
            for (int t = 0; t < 8; ++t) {
                uint32_t b0, b1;
                asm volatile("ldmatrix.sync.aligned.m8n8.x2.trans.shared.b16 {%0,%1}, [%2];"
                             : "=r"(b0), "=r"(b1)
                             : "r"(bAddrBase + (uint32_t)kt * (16 * WSTR_B) + (uint32_t)t * 16));
                asm volatile("mma.sync.aligned.m16n8k16.row.col.f32.bf16.bf16.f32 "
                             "{%0,%1,%2,%3}, {%4,%5,%6,%7}, {%8,%9}, {%0,%1,%2,%3};"
                             : "+f"(acc[t][0]), "+f"(acc[t][1]), "+f"(acc[t][2]), "+f"(acc[t][3])
                             : "r"(a0), "r"(a1), "r"(a2), "r"(a3), "r"(b0), "r"(b1));
            }
        }

        const int j1 = js[m1], j2 = js[m2];
        const float* thp = g_theta + (size_t)(n0 + wp) * CH;
#pragma unroll
        for (int t = 0; t < 8; ++t) {
            int ca = nbase + t * 8 + 2 * (lane & 3);
            float2 th  = *(const float2*)&thp[ca];
            float2 b2  = *(const float2*)&pb2[ca];
            float2 p1  = *(const float2*)&g_phi[(size_t)j1 * CH + ca];
            float2 p2  = *(const float2*)&g_phi[(size_t)j2 * CH + ca];
            float2 gg1 = *(const float2*)&g_gf [(size_t)j1 * CH + ca];
            float2 gg2 = *(const float2*)&g_gf [(size_t)j2 * CH + ca];
            float pe00 = acc[t][0] + b2.x, pe01 = acc[t][1] + b2.y;
            float pe10 = acc[t][2] + b2.x, pe11 = acc[t][3] + b2.y;
            float v00 = fmaf(pe00, th.x - p1.x, pe00) * inv;
            float v01 = fmaf(pe01, th.y - p1.y, pe01) * inv;
            float v10 = fmaf(pe10, th.x - p2.x, pe10) * inv;
            float v11 = fmaf(pe11, th.y - p2.y, pe11) * inv;
            float mx = fmaxf(fmaxf(v00, v01), fmaxf(v10, v11));
#pragma unroll
            for (int off = 4; off <= 16; off <<= 1)
                mx = fmaxf(mx, __shfl_xor_sync(0xffffffffu, mx, off));
            float e00 = __expf(v00 - mx), e01 = __expf(v01 - mx);
            float e10 = __expf(v10 - mx), e11 = __expf(v11 - mx);
            float sa = e00 + e10, sb = e01 + e11;
            float ya = fmaf(e00, gg1.x, e10 * gg2.x);
            float yb = fmaf(e01, gg1.y, e11 * gg2.y);
#pragma unroll
            for (int off = 4; off <= 16; off <<= 1) {
                sa += __shfl_xor_sync(0xffffffffu, sa, off);
                sb += __shfl_xor_sync(0xffffffffu, sb, off);
                ya += __shfl_xor_sync(0xffffffffu, ya, off);
                yb += __shfl_xor_sync(0xffffffffu, yb, off);
            }
            if (lane < 4) {
                uint32_t w0 = splitw(ya / sa);
                uint32_t w1 = splitw(yb / sb);
                *(uint2*)&g_ypack[(size_t)(n0 + wp) * 256 + ca] = make_uint2(w0, w1);
            }
        }
    }
}

// ---------------------------------------------------------------------------
extern "C" void kernel_launch(void* const* d_in, const int* in_sizes, int n_in,
                              void* d_out, int out_size)
{
    const float* coords  = (const float*)d_in[0];
    const float* feats   = (const float*)d_in[1];
    const float* theta_w = (const float*)d_in[2];
    const float* theta_b = (const float*)d_in[3];
    const float* phi_w   = (const float*)d_in[4];
    const float* phi_b   = (const float*)d_in[5];
    const float* g_w     = (const float*)d_in[6];
    const float* g_b     = (const float*)d_in[7];
    const float* pe1_w1  = (const float*)d_in[8];
    const float* pe1_b1  = (const float*)d_in[9];
    const float* pe1_w2  = (const float*)d_in[10];
    const float* pe1_b2  = (const float*)d_in[11];
    const float* W_w     = (const float*)d_in[12];
    const float* W_b     = (const float*)d_in[13];
    float* out = (float*)d_out;

    float *p_theta, *p_phi, *p_g;
    uint32_t *p_fpack, *p_ypack, *p_wpack;
    cudaGetSymbolAddress((void**)&p_theta, g_theta);
    cudaGetSymbolAddress((void**)&p_phi,   g_phi);
    cudaGetSymbolAddress((void**)&p_g,     g_gf);
    cudaGetSymbolAddress((void**)&p_fpack, g_fpack);
    cudaGetSymbolAddress((void**)&p_ypack, g_ypack);
    cudaGetSymbolAddress((void**)&p_wpack, g_wpack);

    cudaFuncSetAttribute((const void*)attn_kernel,
                         cudaFuncAttributeMaxDynamicSharedMemorySize, ATTN_SMEM);

    grid_zero_kernel<<<1, NCELLS>>>();
    grid_count_kernel<<<NPTS / 256, 256>>>(coords);
    prep_w2_kernel<<<128, 256>>>(pe1_w2);
    prep_feats_kernel<<<2048, 256>>>(feats);
    prep_wts_kernel<<<2048, 256>>>(theta_w, phi_w, g_w, W_w);
    grid_prefix_kernel<<<1, NCELLS>>>();
    grid_scatter_kernel<<<NPTS / 256, 256>>>(coords);
    knn_grid_kernel<<<NPTS / 8, 256>>>(coords);

    // fused theta/phi/g GEMM
    gemmsp_kernel<<<dim3(12, NPTS / 128), 256>>>(
        p_fpack, p_wpack, theta_b, phi_b, g_b, p_theta, p_phi, p_g, nullptr);

    attn_kernel<<<NPTS / 8, 256, ATTN_SMEM>>>(coords, pe1_w1, pe1_b1, pe1_b2);

    // W GEMM + residual
    gemmsp_kernel<<<dim3(4, NPTS / 128), 256>>>(
        p_ypack, p_wpack + (size_t)3 * 2 * 4 * 512 * 32,
        W_b, nullptr, nullptr, out, nullptr, nullptr, feats);
}